// round 17
// baseline (speedup 1.0000x reference)
#include <cuda_runtime.h>
#include <cuda.h>
#include <cstdint>
#include <dlfcn.h>

// Model_NPZD_68401649156380 — R17: TMA tiles with 336B row segments.
// gf/gm viewed as (2048, 52, 168) row-major. Block = 1 batch, NT=64.
// TWO chunks of 28 steps: box (84 @ x=84c, 52, 1) per array per chunk,
// both issued at block start (separate mbarriers, no ring reuse).
// Compute reads 3x LDS.128 per 4-step subgroup (lane stride 336B ->
// conflict-free across 8-lane phases) and extracts cols 3i in registers.

#define NB      2048
#define NWK     52
#define NHRS    8760
#define DT      0.125f
#define NT      64
#define TILEF   (NWK * 84)              // 4368 floats per array per chunk
#define TILEB   (TILEF * 4)             // 17472 B (actual TX bytes)
#define TILEBP  17536                   // padded to 128B multiple
#define TILEFP  (TILEBP / 4)            // 4384 floats
#define SLOTB   (2 * TILEBP)            // 35072 B (f tile + m tile)
#define SLOTF   (SLOTB / 4)             // 8768 floats
#define SMEM_BYTES (2 * SLOTB + 128)    // 70272 B -> 3 blocks/SM
#define GRID    NB                      // 2048

__device__ __forceinline__ void mbar_wait(uint32_t mb, uint32_t parity)
{
    uint32_t done;
    asm volatile(
        "{\n\t.reg .pred p;\n\t"
        "mbarrier.try_wait.parity.acquire.cta.shared::cta.b64 p, [%1], %2;\n\t"
        "selp.b32 %0, 1, 0, p;\n\t}"
        : "=r"(done) : "r"(mb), "r"(parity) : "memory");
    if (!done) {
        asm volatile(
            "{\n\t.reg .pred P1;\n\t"
            "W_%=:\n\t"
            "mbarrier.try_wait.parity.acquire.cta.shared::cta.b64 P1, [%0], %1, 0x989680;\n\t"
            "@P1 bra.uni D_%=;\n\t"
            "bra.uni W_%=;\n\t"
            "D_%=:\n\t}"
            :: "r"(mb), "r"(parity) : "memory");
    }
}

__global__ __launch_bounds__(NT) void npzd_tma(
    const __grid_constant__ CUtensorMap tmf,
    const __grid_constant__ CUtensorMap tmm,
    const float* __restrict__ X_in,
    const float* __restrict__ pv,
    float* __restrict__ out)
{
    extern __shared__ float rraw[];
    __shared__ __align__(8) unsigned long long mbar[2];

    const int tid = threadIdx.x;
    const int b   = blockIdx.x;

    // 128B-align the ring base (TMA smem destination requirement).
    uint32_t raw_sh = (uint32_t)__cvta_generic_to_shared(rraw);
    uint32_t rbase  = (raw_sh + 127u) & ~127u;
    float*   ringp  = (float*)((char*)rraw + (rbase - raw_sh));

    const uint32_t mbsh = (uint32_t)__cvta_generic_to_shared(mbar);
    const CUtensorMap* mf = &tmf;
    const CUtensorMap* mm = &tmm;

    if (tid == 0) {
        asm volatile("mbarrier.init.shared.b64 [%0], 1;" :: "r"(mbsh)     : "memory");
        asm volatile("mbarrier.init.shared.b64 [%0], 1;" :: "r"(mbsh + 8) : "memory");
        asm volatile("fence.proxy.async.shared::cta;" ::: "memory");
    }
    __syncthreads();

    // Issue BOTH chunks' TMAs up front (maximal per-block MLP).
    if (tid == 0) {
        #pragma unroll
        for (int c = 0; c < 2; ++c) {
            const uint32_t mb = mbsh + c * 8;
            const uint32_t df = rbase + (uint32_t)(c * SLOTB);
            const uint32_t dm = df + TILEBP;
            asm volatile("mbarrier.arrive.expect_tx.shared.b64 _, [%0], %1;"
                         :: "r"(mb), "r"((uint32_t)(2 * TILEB)) : "memory");
            asm volatile(
                "cp.async.bulk.tensor.3d.shared::cta.global.tile.mbarrier::complete_tx::bytes"
                " [%0], [%1, {%2, %3, %4}], [%5];"
                :: "r"(df), "l"(mf), "r"(84 * c), "r"(0), "r"(b), "r"(mb) : "memory");
            asm volatile(
                "cp.async.bulk.tensor.3d.shared::cta.global.tile.mbarrier::complete_tx::bytes"
                " [%0], [%1, {%2, %3, %4}], [%5];"
                :: "r"(dm), "l"(mm), "r"(84 * c), "r"(0), "r"(b), "r"(mb) : "memory");
        }
    }

    // ---- params + initial state (overlaps TMA flights) ----
    const int w = tid;                  // valid for tid < NWK

    float chiC=0, rho2=0, gam01=0, lam005=0, eps01=0,
          alp03=0, bet06=0, eta015=0, phi04=0, zet01=0, rem=0;
    float N=0, P=0, Z=0, D=0;
    if (tid < NWK) {
        const float* p = pv + b * 10;
        chiC   = p[0];
        rho2   = p[1] * 2.0f;
        gam01  = p[2] * 0.1f;
        lam005 = p[3] * 0.05f;
        eps01  = p[4] * 0.1f;
        alp03  = p[5] * 0.3f;
        bet06  = p[6] * 0.6f;
        eta015 = p[7] * 0.15f;
        phi04  = p[8] * 0.4f;
        zet01  = p[9] * 0.1f;
        rem    = 1.0f - alp03 - bet06;

        const float* xi = X_in + ((size_t)(b * NWK + w)) * 5;
        N = xi[1]; P = xi[2]; Z = xi[3]; D = xi[4];
    }

    float o[4][8];
    o[0][0] = N; o[1][0] = P; o[2][0] = Z; o[3][0] = D;

    #pragma unroll
    for (int c = 0; c < 2; ++c) {
        mbar_wait(mbsh + c * 8, 0u);

        if (tid < NWK) {
            const float* fb = ringp + c * SLOTF + w * 84;
            const float* mb2 = fb + TILEFP;
            // 28 steps = 7 subgroups of 4 steps (12 cols = 3 float4 each).
            #pragma unroll
            for (int sub = 0; sub < 7; ++sub) {
                const float4* f4 = (const float4*)(fb + 12 * sub);
                const float4* m4 = (const float4*)(mb2 + 12 * sub);
                float4 a0 = f4[0], a1 = f4[1], a2 = f4[2];
                float4 c0 = m4[0], c1 = m4[1], c2 = m4[2];
                float fv[4] = {a0.x, a0.w, a1.z, a2.y};
                float mv[4] = {c0.x, c0.w, c1.z, c2.y};

                #pragma unroll
                for (int i = 0; i < 4; ++i) {
                    float ft = fv[i], mt = mv[i];

                    float Pc = fmaxf(0.01f, P);
                    float Zc = fmaxf(0.01f, Z);
                    float gN = N / (chiC + N);
                    float zg = rho2 * (1.0f - __expf(-lam005 * Pc)) * Zc;
                    float up = gN * ft * Pc;                    // Vm = 1

                    float Nn = N + DT * (-up + alp03 * zg + eps01 * P + gam01 * Z
                                         + phi04 * D + mt * (8.0f - N));   // Q0=8
                    float Pn = P + DT * (up - zg - eps01 * P - eta015 * P - mt * P);
                    float Zn = Z + DT * (bet06 * zg - gam01 * Z - mt * Z);
                    float Dn = D + DT * (eta015 * P + rem * zg - phi04 * D
                                         - zet01 * D - mt * D);
                    N = Nn; P = Pn; Z = Zn; D = Dn;

                    const int gs = 28 * c + 4 * sub + i;    // compile-time
                    if (((gs + 1) & 7) == 0) {
                        const int k = (gs + 1) >> 3;
                        o[0][k] = N; o[1][k] = P; o[2][k] = Z; o[3][k] = D;
                    }
                }
            }
        }
    }
    __syncthreads();   // all smem tile reads done; reuse for output transpose

    float* obuf = ringp;                 // 52*33 = 1716 floats, fits
    if (tid < NWK) {
        float* ob = obuf + tid * 33;
        #pragma unroll
        for (int cc = 0; cc < 4; ++cc)
            #pragma unroll
            for (int k = 0; k < 8; ++k)
                ob[cc * 8 + k] = o[cc][k];
    }
    __syncthreads();

    float* outb = out + (size_t)b * (NWK * 32);
    #pragma unroll
    for (int i = tid; i < NWK * 32; i += NT) {
        int t2 = i >> 5;
        int m  = i & 31;
        outb[i] = obuf[t2 * 33 + m];
    }
}

// ======================= Fallback: proven R10 pipeline =======================
#define NCH      7
#define FB_NT    256
#define FB_G     4
#define FB_NCOMP (FB_G * NWK)
#define FB_IPAD  9
#define FB_SLOTF2 (FB_NCOMP * FB_IPAD)
#define FB_SLOTB  (FB_SLOTF2 * 8)
#define FB_SMEM   (3 * FB_SLOTB)
#define FB_CHE    (FB_NCOMP * 8)
#define FB_KMAX   7

__global__ __launch_bounds__(FB_NT, 4) void npzd_fb(
    const float* __restrict__ X_in, const float* __restrict__ gf,
    const float* __restrict__ gm, const float* __restrict__ pv,
    float* __restrict__ out)
{
    extern __shared__ float2 ring[];
    const int tid = threadIdx.x;
    const int b0  = blockIdx.x * FB_G;
    const uint32_t ringsh = (uint32_t)__cvta_generic_to_shared(ring);

    int      srcOff[FB_KMAX];
    uint32_t dstRel[FB_KMAX];
    #pragma unroll
    for (int k = 0; k < FB_KMAX; ++k) {
        int e = tid + FB_NT * k;
        if (e < FB_CHE) {
            int gw = e >> 3, i = e & 7;
            int g = gw / NWK, w = gw - g * NWK;
            srcOff[k] = (b0 + g) * NHRS + 168 * w + 3 * i;
            dstRel[k] = (uint32_t)((gw * FB_IPAD + i) * 8);
        } else { srcOff[k] = 0; dstRel[k] = 0; }
    }
    auto issue = [&](int c, int slot) {
        const uint32_t sb = ringsh + (uint32_t)(slot * FB_SLOTB);
        const int add = 24 * c;
        #pragma unroll
        for (int k = 0; k < FB_KMAX; ++k) {
            if (k == FB_KMAX - 1 && tid >= (FB_CHE - FB_NT * (FB_KMAX - 1))) break;
            uint32_t d = sb + dstRel[k];
            asm volatile("cp.async.ca.shared.global [%0], [%1], 4;\n"
                         :: "r"(d), "l"(gf + (srcOff[k] + add)) : "memory");
            asm volatile("cp.async.ca.shared.global [%0], [%1], 4;\n"
                         :: "r"(d + 4), "l"(gm + (srcOff[k] + add)) : "memory");
        }
        asm volatile("cp.async.commit_group;\n" ::: "memory");
    };
    issue(0, 0); issue(1, 1);

    const int g = tid / NWK, w = tid - g * NWK, b = b0 + g;
    float chiC=0, rho2=0, gam01=0, lam005=0, eps01=0,
          alp03=0, bet06=0, eta015=0, phi04=0, zet01=0, rem=0;
    float N=0, P=0, Z=0, D=0;
    if (tid < FB_NCOMP) {
        const float* p = pv + b * 10;
        chiC = p[0]; rho2 = p[1]*2.0f; gam01 = p[2]*0.1f; lam005 = p[3]*0.05f;
        eps01 = p[4]*0.1f; alp03 = p[5]*0.3f; bet06 = p[6]*0.6f;
        eta015 = p[7]*0.15f; phi04 = p[8]*0.4f; zet01 = p[9]*0.1f;
        rem = 1.0f - alp03 - bet06;
        const float* xi = X_in + ((size_t)(b * NWK + w)) * 5;
        N = xi[1]; P = xi[2]; Z = xi[3]; D = xi[4];
    }
    float o[4][8];
    o[0][0]=N; o[1][0]=P; o[2][0]=Z; o[3][0]=D;
    #pragma unroll 1
    for (int c = 0; c < NCH; ++c) {
        if (c == NCH - 1) asm volatile("cp.async.wait_group 0;\n" ::: "memory");
        else              asm volatile("cp.async.wait_group 1;\n" ::: "memory");
        __syncthreads();
        if (c + 2 < NCH) issue(c + 2, (c + 2) % 3);
        if (tid < FB_NCOMP) {
            const float2* sp = ring + (c % 3) * FB_SLOTF2 + tid * FB_IPAD;
            #pragma unroll
            for (int i = 0; i < 8; ++i) {
                float2 fm = sp[i];
                float ft = fm.x, mt = fm.y;
                float Pc = fmaxf(0.01f, P), Zc = fmaxf(0.01f, Z);
                float gN = N / (chiC + N);
                float zg = rho2 * (1.0f - __expf(-lam005 * Pc)) * Zc;
                float up = gN * ft * Pc;
                float Nn = N + DT*(-up + alp03*zg + eps01*P + gam01*Z + phi04*D + mt*(8.0f - N));
                float Pn = P + DT*(up - zg - eps01*P - eta015*P - mt*P);
                float Zn = Z + DT*(bet06*zg - gam01*Z - mt*Z);
                float Dn = D + DT*(eta015*P + rem*zg - phi04*D - zet01*D - mt*D);
                N = Nn; P = Pn; Z = Zn; D = Dn;
            }
            o[0][c+1]=N; o[1][c+1]=P; o[2][c+1]=Z; o[3][c+1]=D;
        }
    }
    __syncthreads();
    float* obuf = (float*)ring;
    if (tid < FB_NCOMP) {
        float* ob = obuf + tid * 33;
        #pragma unroll
        for (int cc = 0; cc < 4; ++cc)
            #pragma unroll
            for (int k = 0; k < 8; ++k) ob[cc*8 + k] = o[cc][k];
    }
    __syncthreads();
    float* outb = out + (size_t)blockIdx.x * (FB_NCOMP * 32);
    #pragma unroll
    for (int i = tid; i < FB_NCOMP * 32; i += FB_NT)
        outb[i] = obuf[(i >> 5) * 33 + (i & 31)];
}

typedef CUresult (*EncodeFn)(
    CUtensorMap*, CUtensorMapDataType, cuuint32_t, void*,
    const cuuint64_t*, const cuuint64_t*, const cuuint32_t*, const cuuint32_t*,
    CUtensorMapInterleave, CUtensorMapSwizzle, CUtensorMapL2promotion,
    CUtensorMapFloatOOBfill);

extern "C" void kernel_launch(void* const* d_in, const int* in_sizes, int n_in,
                              void* d_out, int out_size)
{
    (void)in_sizes; (void)n_in; (void)out_size;
    const float* X_in = (const float*)d_in[0];
    void*        gf   = (void*)d_in[1];
    void*        gm   = (void*)d_in[2];
    const float* pvv  = (const float*)d_in[3];
    float* out        = (float*)d_out;

    bool tma_ok = false;
    static CUtensorMap tmf, tmm;

    void* h = dlopen("libcuda.so.1", RTLD_NOW | RTLD_GLOBAL);
    if (!h) h = dlopen("libcuda.so", RTLD_NOW | RTLD_GLOBAL);
    EncodeFn enc = h ? (EncodeFn)dlsym(h, "cuTensorMapEncodeTiled") : nullptr;

    if (enc) {
        cuuint64_t dims[3]    = {168, NWK, NB};
        cuuint64_t strides[2] = {168 * 4, (cuuint64_t)NHRS * 4};
        cuuint32_t box[3]     = {84, NWK, 1};
        cuuint32_t estr[3]    = {1, 1, 1};
        CUresult r1 = enc(&tmf, CU_TENSOR_MAP_DATA_TYPE_FLOAT32, 3, gf,
                          dims, strides, box, estr,
                          CU_TENSOR_MAP_INTERLEAVE_NONE, CU_TENSOR_MAP_SWIZZLE_NONE,
                          CU_TENSOR_MAP_L2_PROMOTION_L2_128B,
                          CU_TENSOR_MAP_FLOAT_OOB_FILL_NONE);
        CUresult r2 = enc(&tmm, CU_TENSOR_MAP_DATA_TYPE_FLOAT32, 3, gm,
                          dims, strides, box, estr,
                          CU_TENSOR_MAP_INTERLEAVE_NONE, CU_TENSOR_MAP_SWIZZLE_NONE,
                          CU_TENSOR_MAP_L2_PROMOTION_L2_128B,
                          CU_TENSOR_MAP_FLOAT_OOB_FILL_NONE);
        tma_ok = (r1 == CUDA_SUCCESS && r2 == CUDA_SUCCESS);
    }

    if (tma_ok) {
        cudaFuncSetAttribute(npzd_tma,
                             cudaFuncAttributeMaxDynamicSharedMemorySize,
                             SMEM_BYTES);
        npzd_tma<<<GRID, NT, SMEM_BYTES>>>(tmf, tmm, X_in, pvv, out);
    } else {
        cudaFuncSetAttribute(npzd_fb,
                             cudaFuncAttributeMaxDynamicSharedMemorySize,
                             FB_SMEM);
        npzd_fb<<<NB / FB_G, FB_NT, FB_SMEM>>>(
            X_in, (const float*)gf, (const float*)gm, pvv, out);
    }
}